// round 7
// baseline (speedup 1.0000x reference)
#include <cuda_runtime.h>
#include <cstdint>
#include <cstddef>

#define Bn 16
#define Cn 256
#define Hn 64
#define Wn 64
#define MAXD 4
#define PP 81
#define HW (Hn * Wn)

#define TILE_I 8
#define CC 8
#define NCHUNK (Cn / CC)        // 32
#define YROWS 10                // TILE_I + 2 (3 di per pass)
#define YCOLS 72                // 64 + 2*4 halo
#define NT 256

#define SY_FLOATS (CC * YROWS * YCOLS)   // 5760
#define SY_BYTES  (SY_FLOATS * 4)        // 23040
#define SMEM_TOTAL (2 * SY_BYTES)        // 46080

__device__ __forceinline__ void cp16(uint32_t dst, const void* src) {
    asm volatile("cp.async.cg.shared.global [%0], [%1], 16;\n"
                 :: "r"(dst), "l"(src));
}
__device__ __forceinline__ void cp_commit() {
    asm volatile("cp.async.commit_group;\n" ::: "memory");
}
__device__ __forceinline__ void cp_wait1() {
    asm volatile("cp.async.wait_group 1;\n" ::: "memory");
}
__device__ __forceinline__ void cp_wait0() {
    asm volatile("cp.async.wait_group 0;\n" ::: "memory");
}

__global__ __launch_bounds__(NT, 3)
void corr_kernel(const float* __restrict__ x,
                 const float* __restrict__ y,
                 float* __restrict__ out)
{
    extern __shared__ float smem[];

    const int tid  = threadIdx.x;
    const int lane = tid & 31;          // pixel cols 2*lane, 2*lane+1
    const int tr   = tid >> 5;          // pixel row in tile (warp id), 0..7
    const int i0   = blockIdx.x * TILE_I;
    const int b    = blockIdx.y;
    const int d0   = blockIdx.z * 3;    // di in {d0, d0+1, d0+2}
    const int yrow0 = i0 + d0 - MAXD;   // global row for sy row 0

    const float* xb = x + (size_t)b * Cn * HW;
    const float* yb = y + (size_t)b * Cn * HW;
    const uint32_t sbase = (uint32_t)__cvta_generic_to_shared(smem);

    // ---- zero both y buffers once (halo cols + OOB rows stay zero forever) ----
    {
        float4* s4 = (float4*)smem;
        #pragma unroll
        for (int i = 0; i < SMEM_TOTAL / 16 / NT + 1; i++) {
            int idx = tid + i * NT;
            if (idx < SMEM_TOTAL / 16)
                s4[idx] = make_float4(0.f, 0.f, 0.f, 0.f);
        }
    }
    __syncthreads();

    float acc[3][9][2];
    #pragma unroll
    for (int dl = 0; dl < 3; dl++)
        #pragma unroll
        for (int dj = 0; dj < 9; dj++) {
            acc[dl][dj][0] = 0.f;
            acc[dl][dj][1] = 0.f;
        }

    // ---- issue chunk k's y loads into buffer (k&1) ----
    // 8cc x 10rows x 16 float4 = 1280 float4 -> 5 per thread
    auto issue = [&](int k) {
        const uint32_t syb = sbase + (uint32_t)(k & 1) * SY_BYTES;
        const float* ybk = yb + (size_t)(k * CC) * HW;
        #pragma unroll
        for (int m = 0; m < 5; m++) {
            const int idx = tid + NT * m;       // 0..1279
            const int cc  = idx / 160;          // 160 = 10 rows * 16 quads
            const int rem = idx - cc * 160;
            const int r   = rem >> 4;
            const int q   = rem & 15;
            const int gr  = yrow0 + r;
            if ((unsigned)gr < (unsigned)Hn) {
                const float* src = ybk + (size_t)cc * HW + gr * Wn + q * 4;
                const uint32_t dst = syb +
                    (uint32_t)(((cc * YROWS + r) * YCOLS + 4 + q * 4) * 4);
                cp16(dst, src);
            }
        }
        cp_commit();
    };

    // x: direct LDG.64, one channel ahead (no smem staging: zero reuse)
    const float* xrow = xb + (i0 + tr) * Wn + 2 * lane;
    float2 xv = *(const float2*)xrow;           // channel 0

    issue(0);
    #pragma unroll 1
    for (int k = 0; k < NCHUNK; k++) {
        if (k + 1 < NCHUNK) { issue(k + 1); cp_wait1(); }
        else                { cp_wait0(); }
        __syncthreads();

        const int syo = (k & 1) * SY_FLOATS + tr * YCOLS + 2 * lane;

        #pragma unroll 1
        for (int cc = 0; cc < CC; cc++) {
            const int ch  = k * CC + cc;
            const int chn = (ch + 1 < Cn) ? (ch + 1) : ch;
            const float2 xn = *(const float2*)(xrow + (size_t)chn * HW);

            #pragma unroll
            for (int dl = 0; dl < 3; dl++) {
                const int rbase = syo + (cc * YROWS + dl) * YCOLS;
                float yv[10];
                #pragma unroll
                for (int kk = 0; kk < 5; kk++) {
                    const float2 v = *(const float2*)&smem[rbase + 2 * kk];
                    yv[2 * kk]     = v.x;
                    yv[2 * kk + 1] = v.y;
                }
                #pragma unroll
                for (int dj = 0; dj < 9; dj++) {
                    acc[dl][dj][0] += xv.x * yv[dj];
                    acc[dl][dj][1] += xv.y * yv[dj + 1];
                }
            }
            xv = xn;
        }
        __syncthreads();        // protect buffer (k&1) before issue(k+2)
    }

    // ---- write out: each output element owned by exactly one thread ----
    const float scale = 1.f / (float)Cn;
    const int row = i0 + tr;
    #pragma unroll
    for (int dl = 0; dl < 3; dl++)
        #pragma unroll
        for (int dj = 0; dj < 9; dj++) {
            const int p = (d0 + dl) * 9 + dj;
            float2 v;
            v.x = acc[dl][dj][0] * scale;
            v.y = acc[dl][dj][1] * scale;
            *(float2*)&out[(((size_t)b * PP + p) * Hn + row) * Wn + 2 * lane] = v;
        }
}

extern "C" void kernel_launch(void* const* d_in, const int* in_sizes, int n_in,
                              void* d_out, int out_size)
{
    const float* x = (const float*)d_in[0];
    const float* y = (const float*)d_in[1];
    float* out = (float*)d_out;

    cudaFuncSetAttribute(corr_kernel,
                         cudaFuncAttributeMaxDynamicSharedMemorySize,
                         SMEM_TOTAL);

    dim3 grid(Hn / TILE_I, Bn, 3);   // 8 x 16 x 3 = 384 blocks
    dim3 block(NT);
    corr_kernel<<<grid, block, SMEM_TOTAL>>>(x, y, out);
}

// round 10
// speedup vs baseline: 1.2483x; 1.2483x over previous
#include <cuda_runtime.h>
#include <cstdint>
#include <cstddef>

#define Bn 16
#define Cn 256
#define Hn 64
#define Wn 64
#define MAXD 4
#define PP 81
#define HW (Hn * Wn)

#define TILE_I 8
#define CC 8
#define NCHUNK (Cn / CC)        // 32
#define YROWS 10                // TILE_I + 2 (3 di per pass)
#define YCOLS 72                // 64 + 2*4 halo
#define NT 128
#define TPR 16                  // threads per pixel row (4 cols each)

#define SY_FLOATS (CC * YROWS * YCOLS)   // 5760
#define SY_BYTES  (SY_FLOATS * 4)        // 23040
#define SMEM_TOTAL (2 * SY_BYTES)        // 46080

typedef unsigned long long ull;

__device__ __forceinline__ ull pack2(float lo, float hi) {
    ull r;
    asm("mov.b64 %0, {%1, %2};" : "=l"(r) : "f"(lo), "f"(hi));
    return r;
}
__device__ __forceinline__ ull fma2(ull a, ull b, ull c) {
    ull d;
    asm("fma.rn.f32x2 %0, %1, %2, %3;" : "=l"(d) : "l"(a), "l"(b), "l"(c));
    return d;
}
__device__ __forceinline__ void unpack2(ull v, float& lo, float& hi) {
    asm("mov.b64 {%0, %1}, %2;" : "=f"(lo), "=f"(hi) : "l"(v));
}

__device__ __forceinline__ void cp16(uint32_t dst, const void* src) {
    asm volatile("cp.async.cg.shared.global [%0], [%1], 16;\n"
                 :: "r"(dst), "l"(src));
}
__device__ __forceinline__ void cp_commit() {
    asm volatile("cp.async.commit_group;\n" ::: "memory");
}
__device__ __forceinline__ void cp_wait1() {
    asm volatile("cp.async.wait_group 1;\n" ::: "memory");
}
__device__ __forceinline__ void cp_wait0() {
    asm volatile("cp.async.wait_group 0;\n" ::: "memory");
}

__global__ __launch_bounds__(NT, 3)
void corr_kernel(const float* __restrict__ x,
                 const float* __restrict__ y,
                 float* __restrict__ out)
{
    extern __shared__ float smem[];

    const int tid = threadIdx.x;
    const int tc  = tid & (TPR - 1);    // pixel cols 4tc .. 4tc+3
    const int tr  = tid >> 4;           // pixel row in tile, 0..7
    const int i0  = blockIdx.x * TILE_I;
    const int b   = blockIdx.y;
    const int d0  = blockIdx.z * 3;     // di in {d0, d0+1, d0+2}
    const int yrow0 = i0 + d0 - MAXD;   // global row for sy row 0

    const float* xb = x + (size_t)b * Cn * HW;
    const float* yb = y + (size_t)b * Cn * HW;
    const uint32_t sbase = (uint32_t)__cvta_generic_to_shared(smem);

    // ---- zero both y buffers once (halo cols + OOB rows stay zero) ----
    {
        float4* s4 = (float4*)smem;
        #pragma unroll
        for (int i = 0; i < SMEM_TOTAL / 16 / NT + 1; i++) {
            int idx = tid + i * NT;
            if (idx < SMEM_TOTAL / 16)
                s4[idx] = make_float4(0.f, 0.f, 0.f, 0.f);
        }
    }
    __syncthreads();

    // Rotated-basis packed accumulators, per dl (3) and pair-index k (5):
    //   eA[k] = (col0[2k],   col1[2k])    += (x0,x1) * p[k]
    //   rA[k] = (col1[2k-1], col0[2k+1])  += (x1,x0) * p[k]
    //   eB[k] = (col2[2k],   col3[2k])    += (x2,x3) * p[k+1]
    //   rB[k] = (col3[2k-1], col2[2k+1])  += (x3,x2) * p[k+1]
    // where p[k] = (y[2k], y[2k+1]) are ALIGNED pairs: no y packing needed.
    ull eA[3][5], rA[3][5], eB[3][5], rB[3][5];
    #pragma unroll
    for (int dl = 0; dl < 3; dl++)
        #pragma unroll
        for (int k = 0; k < 5; k++) {
            eA[dl][k] = 0ull; rA[dl][k] = 0ull;
            eB[dl][k] = 0ull; rB[dl][k] = 0ull;
        }

    // ---- issue chunk k's y loads into buffer (k&1) ----
    // 8cc x 10rows x 16 float4 = 1280 float4 -> 10 per thread
    auto issue = [&](int k) {
        const uint32_t syb = sbase + (uint32_t)(k & 1) * SY_BYTES;
        const float* ybk = yb + (size_t)(k * CC) * HW;
        #pragma unroll
        for (int m = 0; m < 10; m++) {
            const int idx = tid + NT * m;       // 0..1279
            const int cc  = idx / 160;          // 160 = 10 rows * 16 quads
            const int rem = idx - cc * 160;
            const int r   = rem >> 4;
            const int q   = rem & 15;
            const int gr  = yrow0 + r;
            if ((unsigned)gr < (unsigned)Hn) {
                const float* src = ybk + (size_t)cc * HW + gr * Wn + q * 4;
                const uint32_t dst = syb +
                    (uint32_t)(((cc * YROWS + r) * YCOLS + 4 + q * 4) * 4);
                cp16(dst, src);
            }
        }
        cp_commit();
    };

    // x: direct LDG.128, one channel ahead (no smem staging: zero reuse)
    const float* xrow = xb + (i0 + tr) * Wn + 4 * tc;
    float4 xv = *(const float4*)xrow;           // channel 0

    issue(0);
    #pragma unroll 1
    for (int k = 0; k < NCHUNK; k++) {
        if (k + 1 < NCHUNK) { issue(k + 1); cp_wait1(); }
        else                { cp_wait0(); }
        __syncthreads();

        const float* syt = smem + (k & 1) * SY_FLOATS + tr * YCOLS + 4 * tc;

        #pragma unroll 1
        for (int cc = 0; cc < CC; cc++) {
            const int ch  = k * CC + cc;
            const int chn = (ch + 1 < Cn) ? (ch + 1) : ch;
            const float4 xn = *(const float4*)(xrow + (size_t)chn * HW);

            const ull xp = pack2(xv.x, xv.y);   // (x0,x1)
            const ull xs = pack2(xv.y, xv.x);   // (x1,x0)
            const ull xq = pack2(xv.z, xv.w);   // (x2,x3)
            const ull xt = pack2(xv.w, xv.z);   // (x3,x2)

            #pragma unroll
            for (int dl = 0; dl < 3; dl++) {
                const ulonglong2* yp = (const ulonglong2*)
                    (syt + (cc * YROWS + dl) * YCOLS);
                const ulonglong2 v0 = yp[0];    // p0, p1
                const ulonglong2 v1 = yp[1];    // p2, p3
                const ulonglong2 v2 = yp[2];    // p4, p5
                const ull p0 = v0.x, p1 = v0.y;
                const ull p2 = v1.x, p3 = v1.y;
                const ull p4 = v2.x, p5 = v2.y;

                eA[dl][0] = fma2(xp, p0, eA[dl][0]);
                eA[dl][1] = fma2(xp, p1, eA[dl][1]);
                eA[dl][2] = fma2(xp, p2, eA[dl][2]);
                eA[dl][3] = fma2(xp, p3, eA[dl][3]);
                eA[dl][4] = fma2(xp, p4, eA[dl][4]);

                rA[dl][0] = fma2(xs, p0, rA[dl][0]);
                rA[dl][1] = fma2(xs, p1, rA[dl][1]);
                rA[dl][2] = fma2(xs, p2, rA[dl][2]);
                rA[dl][3] = fma2(xs, p3, rA[dl][3]);
                rA[dl][4] = fma2(xs, p4, rA[dl][4]);

                eB[dl][0] = fma2(xq, p1, eB[dl][0]);
                eB[dl][1] = fma2(xq, p2, eB[dl][1]);
                eB[dl][2] = fma2(xq, p3, eB[dl][2]);
                eB[dl][3] = fma2(xq, p4, eB[dl][3]);
                eB[dl][4] = fma2(xq, p5, eB[dl][4]);

                rB[dl][0] = fma2(xt, p1, rB[dl][0]);
                rB[dl][1] = fma2(xt, p2, rB[dl][1]);
                rB[dl][2] = fma2(xt, p3, rB[dl][2]);
                rB[dl][3] = fma2(xt, p4, rB[dl][3]);
                rB[dl][4] = fma2(xt, p5, rB[dl][4]);
            }
            xv = xn;
        }
        __syncthreads();        // protect buffer (k&1) before issue(k+2)
    }

    // ---- epilogue: reassemble 27 float4 outputs per thread ----
    const float scale = 1.f / (float)Cn;
    const int row = i0 + tr;
    #pragma unroll
    for (int dl = 0; dl < 3; dl++) {
        // unpack accumulators for this dl
        float ea[5][2], ra[5][2], eb[5][2], rb[5][2];
        #pragma unroll
        for (int kk = 0; kk < 5; kk++) {
            unpack2(eA[dl][kk], ea[kk][0], ea[kk][1]);
            unpack2(rA[dl][kk], ra[kk][0], ra[kk][1]);
            unpack2(eB[dl][kk], eb[kk][0], eb[kk][1]);
            unpack2(rB[dl][kk], rb[kk][0], rb[kk][1]);
        }
        #pragma unroll
        for (int dj = 0; dj < 9; dj++) {
            const int p = (d0 + dl) * 9 + dj;
            float4 v;
            if ((dj & 1) == 0) {
                const int kk = dj >> 1;
                v.x = ea[kk][0]; v.y = ea[kk][1];
                v.z = eb[kk][0]; v.w = eb[kk][1];
            } else {
                const int kk = dj >> 1;      // dj = 2k+1
                v.x = ra[kk][1];             // col0[2k+1] = rA[k].hi
                v.y = ra[kk + 1][0];         // col1[2k+1] = rA[k+1].lo
                v.z = rb[kk][1];             // col2[2k+1] = rB[k].hi
                v.w = rb[kk + 1][0];         // col3[2k+1] = rB[k+1].lo
            }
            v.x *= scale; v.y *= scale; v.z *= scale; v.w *= scale;
            *(float4*)&out[(((size_t)b * PP + p) * Hn + row) * Wn + 4 * tc] = v;
        }
    }
}

extern "C" void kernel_launch(void* const* d_in, const int* in_sizes, int n_in,
                              void* d_out, int out_size)
{
    const float* x = (const float*)d_in[0];
    const float* y = (const float*)d_in[1];
    float* out = (float*)d_out;

    cudaFuncSetAttribute(corr_kernel,
                         cudaFuncAttributeMaxDynamicSharedMemorySize,
                         SMEM_TOTAL);

    dim3 grid(Hn / TILE_I, Bn, 3);   // 8 x 16 x 3 = 384 blocks
    dim3 block(NT);
    corr_kernel<<<grid, block, SMEM_TOTAL>>>(x, y, out);
}